// round 16
// baseline (speedup 1.0000x reference)
#include <cuda_runtime.h>
#include <cuda_bf16.h>
#include <cstdint>

// ---------------------------------------------------------------------------
// Mamba2 layer (B=4, L=2048, d_model=512, d_inner=1024, d_state=128, nheads=1)
// R15: R14 + pass-major MMA ordering in gemm_mma (breaks acc RAW chains:
// same accumulator now updated at dependency distance 16 MMAs, not 1).
// ---------------------------------------------------------------------------

typedef unsigned long long ull;

#define BATCH   4
#define SEQ     2048
#define TOK     (BATCH * SEQ)        // 8192
#define DMODEL  512
#define DINNER  1024
#define DSTATE  128
#define NPROJ   2304
#define PLD     2308
#define CONVCH  1280
#define CH      128                  // chunk length
#define NCHUNK  16                   // chunks per batch
#define BJ      (BATCH * NCHUNK)     // 64 (b,chunk) pairs; token base = bj*128

// ---------------- scratch ----------------
__device__ float g_proj [(size_t)TOK * PLD];
__device__ float g_xconv[(size_t)TOK * CONVCH];
__device__ float g_dt   [TOK];
__device__ float g_la   [TOK];
__device__ float g_yraw [(size_t)TOK * DINNER];
__device__ __nv_bfloat16 g_xhi [(size_t)TOK * DMODEL];
__device__ __nv_bfloat16 g_xlo [(size_t)TOK * DMODEL];
__device__ __nv_bfloat16 g_wihi[(size_t)NPROJ * DMODEL];
__device__ __nv_bfloat16 g_wilo[(size_t)NPROJ * DMODEL];
__device__ __nv_bfloat16 g_yhi [(size_t)TOK * DINNER];
__device__ __nv_bfloat16 g_ylo [(size_t)TOK * DINNER];
__device__ __nv_bfloat16 g_wohi[(size_t)DMODEL * DINNER];
__device__ __nv_bfloat16 g_wolo[(size_t)DMODEL * DINNER];
// chunked-SSD buffers
__device__ __nv_bfloat16 g_acat_hi[(size_t)BJ * CH * 256];      // [M | P_i*C]
__device__ __nv_bfloat16 g_acat_lo[(size_t)BJ * CH * 256];
__device__ __nv_bfloat16 g_bcat_hi[(size_t)BJ * DINNER * 256];  // [U^T | h_in]
__device__ __nv_bfloat16 g_bcat_lo[(size_t)BJ * DINNER * 256];
__device__ __nv_bfloat16 g_u2t_hi [(size_t)BJ * DINNER * CH];   // (W1*u)^T
__device__ __nv_bfloat16 g_u2t_lo [(size_t)BJ * DINNER * CH];
__device__ __nv_bfloat16 g_bt2_hi [(size_t)BJ * DSTATE * CH];   // B^T
__device__ __nv_bfloat16 g_bt2_lo [(size_t)BJ * DSTATE * CH];
__device__ float g_sstate[(size_t)BJ * DINNER * DSTATE];        // chunk state incr
__device__ float g_w1[BJ * CH];                                 // exp(Llast-Ls)
__device__ float g_dj[BJ];                                      // exp(Llast)

// ---------------- cp.async helpers ----------------
__device__ __forceinline__ void cp_async16(void* smem, const void* gmem) {
    uint32_t s = (uint32_t)__cvta_generic_to_shared(smem);
    asm volatile("cp.async.cg.shared.global [%0], [%1], 16;\n" :: "r"(s), "l"(gmem));
}
__device__ __forceinline__ void cp_commit() {
    asm volatile("cp.async.commit_group;\n" ::);
}
template <int N>
__device__ __forceinline__ void cp_wait() {
    asm volatile("cp.async.wait_group %0;\n" :: "n"(N));
}

// ---------------- mma.sync helpers ----------------
__device__ __forceinline__ void ldsm4(uint32_t& r0, uint32_t& r1, uint32_t& r2,
                                      uint32_t& r3, uint32_t addr) {
    asm volatile("ldmatrix.sync.aligned.m8n8.x4.shared.b16 {%0,%1,%2,%3}, [%4];"
                 : "=r"(r0), "=r"(r1), "=r"(r2), "=r"(r3) : "r"(addr));
}
__device__ __forceinline__ void mma16816(float* c, const uint32_t* a, const uint32_t* b) {
    asm volatile(
        "mma.sync.aligned.m16n8k16.row.col.f32.bf16.bf16.f32 "
        "{%0,%1,%2,%3}, {%4,%5,%6,%7}, {%8,%9}, {%0,%1,%2,%3};"
        : "+f"(c[0]), "+f"(c[1]), "+f"(c[2]), "+f"(c[3])
        : "r"(a[0]), "r"(a[1]), "r"(a[2]), "r"(a[3]), "r"(b[0]), "r"(b[1]));
}

__device__ __forceinline__ __nv_bfloat162 split_hi2(float a, float b) {
    return __nv_bfloat162(__float2bfloat16(a), __float2bfloat16(b));
}
__device__ __forceinline__ __nv_bfloat162 split_lo2(float a, float b) {
    float ra = a - __bfloat162float(__float2bfloat16(a));
    float rb = b - __bfloat162float(__float2bfloat16(b));
    return __nv_bfloat162(__float2bfloat16(ra), __float2bfloat16(rb));
}

// ---------------------------------------------------------------------------
// HMMA bf16x3 GEMM (batched): C = A*B^T per batch z. K-major rows everywhere.
// 128x128 CTA tile, BK=32, 256 thr, cp.async double-buffered.
// Per k-step: batch-load all fragments, then pass-major MMA issue (hh, hl, lh)
// so each accumulator's updates are 16 MMAs apart.
// ---------------------------------------------------------------------------
#define BM 128
#define BN 128
#define BK 32
#define SK 40
#define TILE_ELEMS (BM * SK)
#define GEMM_SMEM (2 * 4 * TILE_ELEMS * 2)   // 81920 bytes

__global__ void __launch_bounds__(256, 2)
gemm_mma(const __nv_bfloat16* __restrict__ Ahi, const __nv_bfloat16* __restrict__ Alo,
         const __nv_bfloat16* __restrict__ Bhi, const __nv_bfloat16* __restrict__ Blo,
         float* __restrict__ C, int K, int ldc,
         size_t bsA, size_t bsB, size_t bsC)
{
    extern __shared__ __align__(128) __nv_bfloat16 sm[];
    const int tid  = threadIdx.x;
    const int wid  = tid >> 5;
    const int lane = tid & 31;
    const int wm   = wid >> 1;
    const int wn   = wid & 1;
    const int mb   = blockIdx.y * BM;
    const int nb   = blockIdx.x * BN;
    const size_t zA = (size_t)blockIdx.z * bsA;
    const size_t zB = (size_t)blockIdx.z * bsB;
    const size_t zC = (size_t)blockIdx.z * bsC;
    const uint32_t sbase = (uint32_t)__cvta_generic_to_shared(sm);

    const __nv_bfloat16* gsrc[4] = {
        Ahi + zA + (size_t)mb * K, Alo + zA + (size_t)mb * K,
        Bhi + zB + (size_t)nb * K, Blo + zB + (size_t)nb * K };

    auto load_chunk = [&](int c, int buf) {
        const int k0 = c * BK;
#pragma unroll
        for (int mat = 0; mat < 4; mat++) {
            __nv_bfloat16* dst = sm + (buf * 4 + mat) * TILE_ELEMS;
            const __nv_bfloat16* src = gsrc[mat] + k0;
#pragma unroll
            for (int r = 0; r < 2; r++) {
                const int idx = tid + r * 256;
                const int row = idx >> 2;
                const int seg = idx & 3;
                cp_async16(dst + row * SK + seg * 8, src + (size_t)row * K + seg * 8);
            }
        }
    };

    float acc[2][8][4];
#pragma unroll
    for (int i = 0; i < 2; i++)
#pragma unroll
        for (int j = 0; j < 8; j++)
#pragma unroll
            for (int q = 0; q < 4; q++) acc[i][j][q] = 0.f;

    const int NC = K / BK;
    load_chunk(0, 0); cp_commit();

    const int arow = (lane & 15);
    const int akof = (lane >> 4) << 3;
    const int brow = ((lane >> 4) << 3) + (lane & 7);
    const int bkof = ((lane >> 3) & 1) << 3;

    for (int c = 0; c < NC; ++c) {
        if (c + 1 < NC) { load_chunk(c + 1, (c + 1) & 1); cp_commit(); cp_wait<1>(); }
        else           { cp_wait<0>(); }
        __syncthreads();

        const int buf = c & 1;
        const uint32_t aHi = sbase + (buf * 4 + 0) * TILE_ELEMS * 2;
        const uint32_t aLo = sbase + (buf * 4 + 1) * TILE_ELEMS * 2;
        const uint32_t bHi = sbase + (buf * 4 + 2) * TILE_ELEMS * 2;
        const uint32_t bLo = sbase + (buf * 4 + 3) * TILE_ELEMS * 2;

#pragma unroll
        for (int ks = 0; ks < 2; ks++) {
            // ---- batch-load ALL fragments for this k-step ----
            uint32_t ah[2][4], al[2][4];
#pragma unroll
            for (int mf = 0; mf < 2; mf++) {
                const uint32_t off =
                    (uint32_t)((wm * 32 + mf * 16 + arow) * SK + ks * 16 + akof) * 2;
                ldsm4(ah[mf][0], ah[mf][1], ah[mf][2], ah[mf][3], aHi + off);
                ldsm4(al[mf][0], al[mf][1], al[mf][2], al[mf][3], aLo + off);
            }
            uint32_t bh[4][4], bl[4][4];
#pragma unroll
            for (int nf2 = 0; nf2 < 4; nf2++) {
                const uint32_t off =
                    (uint32_t)((wn * 64 + nf2 * 16 + brow) * SK + ks * 16 + bkof) * 2;
                ldsm4(bh[nf2][0], bh[nf2][1], bh[nf2][2], bh[nf2][3], bHi + off);
                ldsm4(bl[nf2][0], bl[nf2][1], bl[nf2][2], bl[nf2][3], bLo + off);
            }
            // ---- pass-major MMA issue: hh, hl, lh ----
#pragma unroll
            for (int nf2 = 0; nf2 < 4; nf2++)
#pragma unroll
                for (int h = 0; h < 2; h++)
#pragma unroll
                    for (int mf = 0; mf < 2; mf++)
                        mma16816(acc[mf][nf2 * 2 + h], ah[mf], &bh[nf2][h * 2]);
#pragma unroll
            for (int nf2 = 0; nf2 < 4; nf2++)
#pragma unroll
                for (int h = 0; h < 2; h++)
#pragma unroll
                    for (int mf = 0; mf < 2; mf++)
                        mma16816(acc[mf][nf2 * 2 + h], ah[mf], &bl[nf2][h * 2]);
#pragma unroll
            for (int nf2 = 0; nf2 < 4; nf2++)
#pragma unroll
                for (int h = 0; h < 2; h++)
#pragma unroll
                    for (int mf = 0; mf < 2; mf++)
                        mma16816(acc[mf][nf2 * 2 + h], al[mf], &bh[nf2][h * 2]);
        }
        __syncthreads();
    }

#pragma unroll
    for (int mf = 0; mf < 2; mf++) {
        const int r0 = mb + wm * 32 + mf * 16 + (lane >> 2);
#pragma unroll
        for (int nf = 0; nf < 8; nf++) {
            const int col = nb + wn * 64 + nf * 8 + (lane & 3) * 2;
            *(float2*)(C + zC + (size_t)r0 * ldc + col) =
                make_float2(acc[mf][nf][0], acc[mf][nf][1]);
            *(float2*)(C + zC + (size_t)(r0 + 8) * ldc + col) =
                make_float2(acc[mf][nf][2], acc[mf][nf][3]);
        }
    }
}

// ---------------------------------------------------------------------------
// fp32 split -> (hi, lo) bf16
// ---------------------------------------------------------------------------
__global__ void split_bf16(const float* __restrict__ src,
                           __nv_bfloat16* __restrict__ hi,
                           __nv_bfloat16* __restrict__ lo, int n)
{
    const int i = blockIdx.x * 256 + threadIdx.x;
    if (i >= n) return;
    const float v = src[i];
    const __nv_bfloat16 h = __float2bfloat16(v);
    hi[i] = h;
    lo[i] = __float2bfloat16(v - __bfloat162float(h));
}

// ---------------------------------------------------------------------------
// dt GEMV (exact fp32) + softplus; la = dt*A (A = -exp(A_log))
// ---------------------------------------------------------------------------
__global__ void dtprep(const float* __restrict__ x,
                       const float* __restrict__ Wrow,
                       const float* __restrict__ dt_bias,
                       const float* __restrict__ A_log,
                       float* __restrict__ gdt, float* __restrict__ gla)
{
    const int t    = blockIdx.x * 8 + (threadIdx.x >> 5);
    const int lane = threadIdx.x & 31;
    const float* xr = x + (size_t)t * DMODEL;
    float s = 0.f;
#pragma unroll
    for (int i = 0; i < 16; i++)
        s += xr[lane + 32 * i] * Wrow[lane + 32 * i];
#pragma unroll
    for (int m = 16; m; m >>= 1) s += __shfl_xor_sync(0xffffffffu, s, m);
    if (lane == 0) {
        const float raw = s + dt_bias[0];
        const float dt  = (raw > 20.f) ? raw : log1pf(expf(raw));
        gdt[t] = dt;
        gla[t] = dt * (-expf(A_log[0]));
    }
}

// ---------------------------------------------------------------------------
// causal depthwise conv1d (width 4) + bias + silu, sliding window.
// ---------------------------------------------------------------------------
__global__ void conv_silu(const float* __restrict__ proj,
                          const float* __restrict__ cw,
                          const float* __restrict__ cb,
                          float* __restrict__ xconv)
{
    const int id = blockIdx.x * 256 + threadIdx.x;
    if (id >= (TOK / 4) * CONVCH) return;
    const int c    = id % CONVCH;
    const int q    = id / CONVCH;
    const int tkn0 = q * 4;
    const int l0   = tkn0 & (SEQ - 1);

    const float4 w = ((const float4*)cw)[c];
    const float  b = cb[c];
    const size_t col = (size_t)tkn0 * PLD + DINNER + c;

    float v[7];
#pragma unroll
    for (int j = 0; j < 7; j++) {
        const int dl = j - 3;
        v[j] = (l0 + dl >= 0) ? proj[col + (ptrdiff_t)dl * PLD] : 0.f;
    }
#pragma unroll
    for (int j = 0; j < 4; j++) {
        float acc = b + w.x * v[j] + w.y * v[j + 1] + w.z * v[j + 2] + w.w * v[j + 3];
        acc = acc / (1.f + expf(-acc));
        xconv[(size_t)(tkn0 + j) * CONVCH + c] = acc;
    }
}

// ---------------------------------------------------------------------------
// S1 chunk_prep: per (b,j): L cumsum; G=C@B^T (fp32); M=G*exp(Li-Ls)*mask;
// Acat = [M | exp(Li)*C] hi/lo; W1[s]=exp(Llast-Ls); Dj=exp(Llast).
// ---------------------------------------------------------------------------
#define S1_SMEM (2 * 128 * 132 * 4 + 1024)
__global__ void __launch_bounds__(256)
chunk_prep(const float* __restrict__ xconv, const float* __restrict__ gla,
           __nv_bfloat16* __restrict__ acat_hi, __nv_bfloat16* __restrict__ acat_lo,
           float* __restrict__ W1, float* __restrict__ Dj)
{
    extern __shared__ float s1[];
    float* BT  = s1;                    // [n][s] stride 132
    float* Csm = s1 + 128 * 132;        // [i][n] stride 132
    float* sL  = Csm + 128 * 132;       // [128]
    float* sla = sL + 128;              // [128]
    const int bj  = blockIdx.x;
    const int tid = threadIdx.x;
    const int t0  = bj * CH;

    for (int idx = tid; idx < CH * DSTATE; idx += 256) {
        const int s = idx >> 7, n = idx & 127;
        const float* row = xconv + (size_t)(t0 + s) * CONVCH + DINNER;
        BT[n * 132 + s]  = row[n];
        Csm[s * 132 + n] = row[DSTATE + n];
    }
    if (tid < 128) sla[tid] = gla[t0 + tid];
    __syncthreads();
    if (tid == 0) {
        float run = 0.f;
        for (int i = 0; i < CH; i++) { run += sla[i]; sL[i] = run; }
    }
    __syncthreads();

    const int i     = tid & 127;
    const int sbase = (tid >> 7) * 64;
    float acc[64];
#pragma unroll
    for (int k = 0; k < 64; k++) acc[k] = 0.f;
    for (int n = 0; n < 128; n++) {
        const float c = Csm[i * 132 + n];
        const float4* bt = (const float4*)&BT[n * 132 + sbase];
#pragma unroll
        for (int k4 = 0; k4 < 16; k4++) {
            const float4 b4 = bt[k4];
            acc[k4 * 4 + 0] += c * b4.x;
            acc[k4 * 4 + 1] += c * b4.y;
            acc[k4 * 4 + 2] += c * b4.z;
            acc[k4 * 4 + 3] += c * b4.w;
        }
    }
    const float Li = sL[i];
#pragma unroll
    for (int k = 0; k < 64; k++) {
        const int s = sbase + k;
        const float m = (s <= i) ? acc[k] * expf(Li - sL[s]) : 0.f;
        const __nv_bfloat16 h = __float2bfloat16(m);
        const size_t o = ((size_t)bj * CH + i) * 256 + s;
        acat_hi[o] = h;
        acat_lo[o] = __float2bfloat16(m - __bfloat162float(h));
    }
    for (int idx = tid; idx < CH * DSTATE; idx += 256) {
        const int ii = idx >> 7, n = idx & 127;
        const float v = expf(sL[ii]) * Csm[ii * 132 + n];
        const __nv_bfloat16 h = __float2bfloat16(v);
        const size_t o = ((size_t)bj * CH + ii) * 256 + 128 + n;
        acat_hi[o] = h;
        acat_lo[o] = __float2bfloat16(v - __bfloat162float(h));
    }
    if (tid < 128) W1[bj * CH + tid] = expf(sL[127] - sL[tid]);
    if (tid == 0)  Dj[bj] = expf(sL[127]);
}

// ---------------------------------------------------------------------------
// uprep: U = dt*x transposed into Bcat cols 0:128 and W1-scaled into U2t.
// ---------------------------------------------------------------------------
__global__ void __launch_bounds__(256)
uprep(const float* __restrict__ xconv, const float* __restrict__ gdt,
      const float* __restrict__ W1,
      __nv_bfloat16* __restrict__ bcat_hi, __nv_bfloat16* __restrict__ bcat_lo,
      __nv_bfloat16* __restrict__ u2t_hi,  __nv_bfloat16* __restrict__ u2t_lo)
{
    __shared__ float su[64 * 136];
    __shared__ float sw[128];
    __shared__ float sdt[128];
    const int bj    = blockIdx.y;
    const int pbase = blockIdx.x * 64;
    const int tid   = threadIdx.x;
    const int t0    = bj * CH;

    if (tid < 128) { sw[tid] = W1[bj * CH + tid]; sdt[tid] = gdt[t0 + tid]; }
    __syncthreads();
    for (int idx = tid; idx < 64 * 128; idx += 256) {
        const int s = idx >> 6, p = idx & 63;
        su[p * 136 + s] = sdt[s] * xconv[(size_t)(t0 + s) * CONVCH + pbase + p];
    }
    __syncthreads();
    for (int idx = tid; idx < 64 * 64; idx += 256) {
        const int p = idx >> 6, s2 = idx & 63, s = s2 * 2;
        const float2 u = *(const float2*)&su[p * 136 + s];
        const size_t rB = ((size_t)bj * DINNER + pbase + p) * 256 + s;
        *(__nv_bfloat162*)&bcat_hi[rB] = split_hi2(u.x, u.y);
        *(__nv_bfloat162*)&bcat_lo[rB] = split_lo2(u.x, u.y);
        const float v0 = u.x * sw[s], v1 = u.y * sw[s + 1];
        const size_t rU = ((size_t)bj * DINNER + pbase + p) * 128 + s;
        *(__nv_bfloat162*)&u2t_hi[rU] = split_hi2(v0, v1);
        *(__nv_bfloat162*)&u2t_lo[rU] = split_lo2(v0, v1);
    }
}

// ---------------------------------------------------------------------------
// bprep: B chunk transposed -> Bt2[n][s] hi/lo.
// ---------------------------------------------------------------------------
#define BPREP_SMEM (128 * 136 * 4)
__global__ void __launch_bounds__(256)
bprep(const float* __restrict__ xconv,
      __nv_bfloat16* __restrict__ bt2_hi, __nv_bfloat16* __restrict__ bt2_lo)
{
    extern __shared__ float sb[];
    const int bj  = blockIdx.x;
    const int tid = threadIdx.x;
    const int t0  = bj * CH;
    for (int idx = tid; idx < 128 * 128; idx += 256) {
        const int s = idx >> 7, n = idx & 127;
        sb[n * 136 + s] = xconv[(size_t)(t0 + s) * CONVCH + DINNER + n];
    }
    __syncthreads();
    for (int idx = tid; idx < 128 * 64; idx += 256) {
        const int n = idx >> 6, s2 = idx & 63, s = s2 * 2;
        const float2 v = *(const float2*)&sb[n * 136 + s];
        const size_t o = ((size_t)bj * DSTATE + n) * 128 + s;
        *(__nv_bfloat162*)&bt2_hi[o] = split_hi2(v.x, v.y);
        *(__nv_bfloat162*)&bt2_lo[o] = split_lo2(v.x, v.y);
    }
}

// ---------------------------------------------------------------------------
// state_scan: h recurrence over 16 chunks -> h_in into Bcat cols 128:256.
// ---------------------------------------------------------------------------
__global__ void __launch_bounds__(256)
state_scan(const float* __restrict__ S, const float* __restrict__ Dj,
           __nv_bfloat16* __restrict__ bcat_hi, __nv_bfloat16* __restrict__ bcat_lo)
{
    const int idx = blockIdx.x * 256 + threadIdx.x;
    const int b   = idx >> 16;
    const int rem = idx & 65535;
    const int p   = rem >> 6;
    const int n   = (rem & 63) * 2;
    float2 h = make_float2(0.f, 0.f);
#pragma unroll
    for (int j = 0; j < NCHUNK; j++) {
        const int bj = b * NCHUNK + j;
        const size_t row = ((size_t)bj * DINNER + p) * 256 + 128 + n;
        *(__nv_bfloat162*)&bcat_hi[row] = split_hi2(h.x, h.y);
        *(__nv_bfloat162*)&bcat_lo[row] = split_lo2(h.x, h.y);
        const float d = Dj[bj];
        const float2 sv = *(const float2*)&S[((size_t)bj << 17) + p * 128 + n];
        h.x = d * h.x + sv.x;
        h.y = d * h.y + sv.y;
    }
}

// ---------------------------------------------------------------------------
// y = (yraw + D*x) * silu(z); RMSNorm; emit yhi/ylo bf16 splits directly.
// ---------------------------------------------------------------------------
__global__ void gate_norm(const float* __restrict__ yraw,
                          const float* __restrict__ xconv,
                          const float* __restrict__ proj,
                          const float* __restrict__ normw,
                          const float* __restrict__ Dp,
                          __nv_bfloat16* __restrict__ yhi,
                          __nv_bfloat16* __restrict__ ylo)
{
    const int t   = blockIdx.x;
    const int tid = threadIdx.x;
    const float dval = Dp[0];

    float v[4];
    float ss = 0.f;
#pragma unroll
    for (int j = 0; j < 4; j++) {
        const int p = tid + j * 256;
        const float y = yraw[(size_t)t * DINNER + p]
                      + dval * xconv[(size_t)t * CONVCH + p];
        const float z = proj[(size_t)t * PLD + p];
        const float g = z / (1.f + expf(-z));
        const float val = y * g;
        v[j] = val;
        ss += val * val;
    }
#pragma unroll
    for (int m = 16; m; m >>= 1) ss += __shfl_xor_sync(0xffffffffu, ss, m);

    __shared__ float warpsum[8];
    __shared__ float inv_s;
    if ((tid & 31) == 0) warpsum[tid >> 5] = ss;
    __syncthreads();
    if (tid == 0) {
        float s = 0.f;
#pragma unroll
        for (int i = 0; i < 8; i++) s += warpsum[i];
        inv_s = rsqrtf(s * (1.f / DINNER) + 1e-5f);
    }
    __syncthreads();
    const float inv = inv_s;
#pragma unroll
    for (int j = 0; j < 4; j++) {
        const int p = tid + j * 256;
        const float val = v[j] * inv * normw[p];
        const __nv_bfloat16 h = __float2bfloat16(val);
        yhi[(size_t)t * DINNER + p] = h;
        ylo[(size_t)t * DINNER + p] = __float2bfloat16(val - __bfloat162float(h));
    }
}

// ---------------------------------------------------------------------------
extern "C" void kernel_launch(void* const* d_in, const int* in_sizes, int n_in,
                              void* d_out, int out_size)
{
    const float* x       = (const float*)d_in[0];
    const float* rnn     = (const float*)d_in[1];
    const float* W_in    = (const float*)d_in[2];
    const float* conv_w  = (const float*)d_in[3];
    const float* conv_b  = (const float*)d_in[4];
    const float* dt_bias = (const float*)d_in[5];
    const float* A_log   = (const float*)d_in[6];
    const float* Dp      = (const float*)d_in[7];
    const float* norm_w  = (const float*)d_in[8];
    const float* W_out   = (const float*)d_in[9];
    float* out = (float*)d_out;

    float *proj, *xconv, *gdt, *gla, *yraw, *sstate, *w1, *dj;
    __nv_bfloat16 *xhi, *xlo, *wihi, *wilo, *yhi, *ylo, *wohi, *wolo;
    __nv_bfloat16 *acat_hi, *acat_lo, *bcat_hi, *bcat_lo;
    __nv_bfloat16 *u2t_hi, *u2t_lo, *bt2_hi, *bt2_lo;
    cudaGetSymbolAddress((void**)&proj,    g_proj);
    cudaGetSymbolAddress((void**)&xconv,   g_xconv);
    cudaGetSymbolAddress((void**)&gdt,     g_dt);
    cudaGetSymbolAddress((void**)&gla,     g_la);
    cudaGetSymbolAddress((void**)&yraw,    g_yraw);
    cudaGetSymbolAddress((void**)&xhi,     g_xhi);
    cudaGetSymbolAddress((void**)&xlo,     g_xlo);
    cudaGetSymbolAddress((void**)&wihi,    g_wihi);
    cudaGetSymbolAddress((void**)&wilo,    g_wilo);
    cudaGetSymbolAddress((void**)&yhi,     g_yhi);
    cudaGetSymbolAddress((void**)&ylo,     g_ylo);
    cudaGetSymbolAddress((void**)&wohi,    g_wohi);
    cudaGetSymbolAddress((void**)&wolo,    g_wolo);
    cudaGetSymbolAddress((void**)&acat_hi, g_acat_hi);
    cudaGetSymbolAddress((void**)&acat_lo, g_acat_lo);
    cudaGetSymbolAddress((void**)&bcat_hi, g_bcat_hi);
    cudaGetSymbolAddress((void**)&bcat_lo, g_bcat_lo);
    cudaGetSymbolAddress((void**)&u2t_hi,  g_u2t_hi);
    cudaGetSymbolAddress((void**)&u2t_lo,  g_u2t_lo);
    cudaGetSymbolAddress((void**)&bt2_hi,  g_bt2_hi);
    cudaGetSymbolAddress((void**)&bt2_lo,  g_bt2_lo);
    cudaGetSymbolAddress((void**)&sstate,  g_sstate);
    cudaGetSymbolAddress((void**)&w1,      g_w1);
    cudaGetSymbolAddress((void**)&dj,      g_dj);

    cudaFuncSetAttribute(gemm_mma, cudaFuncAttributeMaxDynamicSharedMemorySize,
                         GEMM_SMEM);
    cudaFuncSetAttribute(chunk_prep, cudaFuncAttributeMaxDynamicSharedMemorySize,
                         S1_SMEM);
    cudaFuncSetAttribute(bprep, cudaFuncAttributeMaxDynamicSharedMemorySize,
                         BPREP_SMEM);

    // 0) bf16 splits of GEMM operands
    split_bf16<<<(TOK * DMODEL + 255) / 256, 256>>>(x, xhi, xlo, TOK * DMODEL);
    split_bf16<<<(NPROJ * DMODEL + 255) / 256, 256>>>(W_in, wihi, wilo, NPROJ * DMODEL);
    split_bf16<<<(DMODEL * DINNER + 255) / 256, 256>>>(W_out, wohi, wolo, DMODEL * DINNER);

    // 1) in-projection
    gemm_mma<<<dim3(NPROJ / 128, TOK / 128, 1), 256, GEMM_SMEM>>>(
        xhi, xlo, wihi, wilo, proj, DMODEL, PLD, 0, 0, 0);

    // 2) dt (exact fp32) + la
    dtprep<<<TOK / 8, 256>>>(x, W_in + (size_t)NPROJ * DMODEL, dt_bias, A_log, gdt, gla);

    // 3) conv + silu (sliding window)
    conv_silu<<<((TOK / 4) * CONVCH + 255) / 256, 256>>>(proj, conv_w, conv_b, xconv);

    // 4) chunked-SSD scan
    chunk_prep<<<BJ, 256, S1_SMEM>>>(xconv, gla, acat_hi, acat_lo, w1, dj);
    uprep<<<dim3(16, BJ), 256>>>(xconv, gdt, w1, bcat_hi, bcat_lo, u2t_hi, u2t_lo);
    bprep<<<BJ, 256, BPREP_SMEM>>>(xconv, bt2_hi, bt2_lo);
    gemm_mma<<<dim3(1, DINNER / 128, BJ), 256, GEMM_SMEM>>>(
        u2t_hi, u2t_lo, bt2_hi, bt2_lo, sstate, 128, DSTATE,
        (size_t)DINNER * 128, (size_t)DSTATE * 128, (size_t)DINNER * DSTATE);
    state_scan<<<1024, 256>>>(sstate, dj, bcat_hi, bcat_lo);
    gemm_mma<<<dim3(DINNER / 128, 1, BJ), 256, GEMM_SMEM>>>(
        acat_hi, acat_lo, bcat_hi, bcat_lo, yraw, 256, DINNER,
        (size_t)CH * 256, (size_t)DINNER * 256, (size_t)CH * DINNER);

    // 5) gate + RMSNorm, emitting bf16 hi/lo directly
    gate_norm<<<TOK, 256>>>(yraw, xconv, proj, norm_w, Dp, yhi, ylo);

    // 6) out-projection
    gemm_mma<<<dim3(DMODEL / 128, TOK / 128, 1), 256, GEMM_SMEM>>>(
        yhi, ylo, wohi, wolo, out, DINNER, DMODEL, 0, 0, 0);

    // 7) rnn_state passthrough
    const int main_elems = TOK * DMODEL;
    if (out_size >= main_elems + BATCH * DMODEL) {
        cudaMemcpyAsync(out + main_elems, rnn, (size_t)BATCH * DMODEL * sizeof(float),
                        cudaMemcpyDeviceToDevice, 0);
    }
}